// round 11
// baseline (speedup 1.0000x reference)
#include <cuda_runtime.h>

// CRF NLL: bidirectional exp-domain scan, TWO same-direction half-chains
// fused per single warp (no CTA barriers; chain B's FMAs fill chain A's
// dependency stalls). E = exp(trans) precomputed by prep_kernel in both
// orientations so chain warps load it with 32 LDG.128 and share one
// 128-register copy between both chains. Exact power-of-2 rescaling.
// Block w<256: forward halves of batches {w, w+256} (P_h).
// Block w>=256: backward co-vector halves of the same batches (u_h).
// answer per batch = log(dot(P_h, u_h)) + scales; rendezvous via g_pair.

constexpr int Bb = 512;
constexpr int Ss = 512;
constexpr int Tt = 64;
constexpr int START = Tt - 2;
constexpr int STOP  = Tt - 1;
constexpr int PD    = 4;
constexpr int HALF  = Bb / 2;   // 256
constexpr float LN2 = 0.69314718055994531f;

__device__ float g_expE [Tt * Tt];   // exp(trans), trans layout [from][to]
__device__ float g_expET[Tt * Tt];   // transpose: [to][from]
__device__ float g_meet[Bb][2][68];  // [.][0]: P_h,64=eF,65=c0,66=gold ; [.][1]: u_h,64=eB
__device__ float g_partial[Bb];
__device__ unsigned g_pair[Bb];      // zero-initialized
__device__ unsigned g_count = 0;

typedef unsigned long long u64;

static __device__ __forceinline__ u64 fma2(u64 a, u64 b, u64 c) {
    u64 d;
    asm("fma.rn.f32x2 %0, %1, %2, %3;" : "=l"(d) : "l"(a), "l"(b), "l"(c));
    return d;
}
static __device__ __forceinline__ u64 add2(u64 a, u64 b) {
    u64 d;
    asm("add.rn.f32x2 %0, %1, %2;" : "=l"(d) : "l"(a), "l"(b));
    return d;
}
static __device__ __forceinline__ u64 pack2(float lo, float hi) {
    u64 d;
    asm("mov.b64 %0, {%1, %2};" : "=l"(d) : "f"(lo), "f"(hi));
    return d;
}
static __device__ __forceinline__ void unpack2(u64 v, float& lo, float& hi) {
    asm("mov.b64 {%0, %1}, %2;" : "=f"(lo), "=f"(hi) : "l"(v));
}
static __device__ __forceinline__ float ldcg(const float* p) {
    float v;
    asm volatile("ld.global.cg.f32 %0, [%1];" : "=f"(v) : "l"(p));
    return v;
}
static __device__ __forceinline__ float warp_sum(float v) {
    #pragma unroll
    for (int off = 16; off > 0; off >>= 1)
        v += __shfl_xor_sync(0xffffffffu, v, off);
    return v;
}
static __device__ __forceinline__ int warp_sum_i(int v) {
    #pragma unroll
    for (int off = 16; off > 0; off >>= 1)
        v += __shfl_xor_sync(0xffffffffu, v, off);
    return v;
}

__global__ void prep_kernel(const float* __restrict__ trans) {
    int i = blockIdx.x * blockDim.x + threadIdx.x;   // 0..4095
    float e = __expf(trans[i]);
    g_expE[i] = e;
    g_expET[(i & (Tt - 1)) * Tt + (i >> 6)] = e;
}

__global__ __launch_bounds__(32) void crf_kernel(
    const float* __restrict__ feats,
    const unsigned char* __restrict__ mask8,
    const int* __restrict__ tags,
    const float* __restrict__ trans,
    float* __restrict__ out)
{
    const bool isF = (blockIdx.x < HALF);
    const int  w   = isF ? blockIdx.x : blockIdx.x - HALF;
    const int  bA  = w;
    const int  bB  = w + HALF;
    const int  lane = threadIdx.x;
    const int  to0  = 2 * lane;

    __shared__ __align__(16) float qA[2][Tt], qB[2][Tt];

    // ---- mask layout probe + lengths for both batches ----
    const int* mask32 = reinterpret_cast<const int*>(mask8);
    const bool is32 = (mask8[0] == 1 && mask8[1] == 0 && mask8[2] == 0 && mask8[3] == 0);

    int cA = 0, cB = 0;
    #pragma unroll
    for (int k = 0; k < Ss / 32; ++k) {
        int s = lane + k * 32;
        int va = is32 ? mask32[bA * Ss + s] : (int)mask8[bA * Ss + s];
        int vb = is32 ? mask32[bB * Ss + s] : (int)mask8[bB * Ss + s];
        cA += (va != 0);
        cB += (vb != 0);
    }
    const int LA = warp_sum_i(cA);
    const int LB = warp_sum_i(cB);
    const int hA = LA / 2, hB = LB / 2;

    const float* fAp = feats + (size_t)bA * Ss * Tt;
    const float* fBp = feats + (size_t)bB * Ss * Tt;

    // ---- E registers (shared orientation for both chains) ----
    const float* Es = isF ? g_expET : g_expE;   // fwd: [to][from]; bwd: [to][from-of-w] = expE rows
    u64 E2a[Tt / 2], E2b[Tt / 2];
    {
        const float4* ra = reinterpret_cast<const float4*>(Es + to0 * Tt);
        const float4* rb = reinterpret_cast<const float4*>(Es + (to0 + 1) * Tt);
        #pragma unroll
        for (int k = 0; k < 16; ++k) {
            float4 v = ra[k];
            E2a[2 * k]     = pack2(v.x, v.y);
            E2a[2 * k + 1] = pack2(v.z, v.w);
            float4 u = rb[k];
            E2b[2 * k]     = pack2(u.x, u.y);
            E2b[2 * k + 1] = pack2(u.z, u.w);
        }
    }

    int   eSumA = 0, eSumB = 0;
    float curA0 = 0.f, curA1 = 0.f, curB0 = 0.f, curB1 = 0.f;

    if (isF) {
        // ---- gold scores (both batches) ----
        const int* tgA = tags + bA * Ss;
        const int* tgB = tags + bB * Ss;
        float ga = 0.f, gb = 0.f;
        for (int s = lane; s < LA; s += 32) {
            int t1 = tgA[s];
            int t0 = (s == 0) ? START : tgA[s - 1];
            ga += fAp[s * Tt + t1] + trans[t0 * Tt + t1];
        }
        for (int s = lane; s < LB; s += 32) {
            int t1 = tgB[s];
            int t0 = (s == 0) ? START : tgB[s - 1];
            gb += fBp[s * Tt + t1] + trans[t0 * Tt + t1];
        }
        const float goldA = warp_sum(ga) + trans[tgA[LA - 1] * Tt + STOP];
        const float goldB = warp_sum(gb) + trans[tgB[LB - 1] * Tt + STOP];

        // ---- init: P_0 = exp(f_0 + T[START,:]) / exp(c0) ----
        const float tS0 = trans[START * Tt];
        const float tSa = trans[START * Tt + to0];
        const float tSb = trans[START * Tt + to0 + 1];
        const float cA0 = fAp[0] + tS0;
        const float cB0 = fBp[0] + tS0;
        {
            float2 f0 = *reinterpret_cast<const float2*>(fAp + to0);
            *reinterpret_cast<float2*>(&qA[0][to0]) =
                make_float2(__expf(f0.x + tSa - cA0), __expf(f0.y + tSb - cA0));
            float2 f1 = *reinterpret_cast<const float2*>(fBp + to0);
            *reinterpret_cast<float2*>(&qB[0][to0]) =
                make_float2(__expf(f1.x + tSa - cB0), __expf(f1.y + tSb - cB0));
        }

        float eA0[PD], eA1[PD], eB0[PD], eB1[PD];
        #pragma unroll
        for (int r = 0; r < PD; ++r) {
            float2 fa = *reinterpret_cast<const float2*>(fAp + (1 + r) * Tt + to0);
            eA0[r] = __expf(fa.x); eA1[r] = __expf(fa.y);
            float2 fbv = *reinterpret_cast<const float2*>(fBp + (1 + r) * Tt + to0);
            eB0[r] = __expf(fbv.x); eB1[r] = __expf(fbv.y);
        }

        // ---- fused forward step (both chains interleaved) ----
        auto fstep2 = [&](int s, int r) {
            const float ea0 = eA0[r], ea1 = eA1[r], eb0 = eB0[r], eb1 = eB1[r];
            // prefetch (rows <= h+PD < Ss: always safe)
            float2 fa = *reinterpret_cast<const float2*>(fAp + (s + PD) * Tt + to0);
            eA0[r] = __expf(fa.x); eA1[r] = __expf(fa.y);
            float2 fbv = *reinterpret_cast<const float2*>(fBp + (s + PD) * Tt + to0);
            eB0[r] = __expf(fbv.x); eB1[r] = __expf(fbv.y);

            __syncwarp();
            const ulonglong2* pA = reinterpret_cast<const ulonglong2*>(qA[(s - 1) & 1]);
            const ulonglong2* pB = reinterpret_cast<const ulonglong2*>(qB[(s - 1) & 1]);

            ulonglong2 vA = pA[0], vB = pB[0];
            float qa0, qb0, td;
            unpack2(vA.x, qa0, td);
            unpack2(vB.x, qb0, td);

            u64 xA0 = fma2(vA.x, E2a[0], 0ull), xA1 = fma2(vA.y, E2a[1], 0ull);
            u64 yA0 = fma2(vA.x, E2b[0], 0ull), yA1 = fma2(vA.y, E2b[1], 0ull);
            u64 xB0 = fma2(vB.x, E2a[0], 0ull), xB1 = fma2(vB.y, E2a[1], 0ull);
            u64 yB0 = fma2(vB.x, E2b[0], 0ull), yB1 = fma2(vB.y, E2b[1], 0ull);
            #pragma unroll
            for (int j = 1; j < 16; ++j) {
                vA = pA[j]; vB = pB[j];
                xA0 = fma2(vA.x, E2a[2 * j],     xA0);
                xB0 = fma2(vB.x, E2a[2 * j],     xB0);
                xA1 = fma2(vA.y, E2a[2 * j + 1], xA1);
                xB1 = fma2(vB.y, E2a[2 * j + 1], xB1);
                yA0 = fma2(vA.x, E2b[2 * j],     yA0);
                yB0 = fma2(vB.x, E2b[2 * j],     yB0);
                yA1 = fma2(vA.y, E2b[2 * j + 1], yA1);
                yB1 = fma2(vB.y, E2b[2 * j + 1], yB1);
            }
            const unsigned ebA = __float_as_uint(qa0) >> 23;
            eSumA += (int)ebA - 127;
            const float scA = __uint_as_float((254u - ebA) << 23);
            const unsigned ebB = __float_as_uint(qb0) >> 23;
            eSumB += (int)ebB - 127;
            const float scB = __uint_as_float((254u - ebB) << 23);

            float lo, hi;
            unpack2(add2(xA0, xA1), lo, hi); curA0 = (lo + hi) * (ea0 * scA);
            unpack2(add2(yA0, yA1), lo, hi); curA1 = (lo + hi) * (ea1 * scA);
            unpack2(add2(xB0, xB1), lo, hi); curB0 = (lo + hi) * (eb0 * scB);
            unpack2(add2(yB0, yB1), lo, hi); curB1 = (lo + hi) * (eb1 * scB);
            *reinterpret_cast<float2*>(&qA[s & 1][to0]) = make_float2(curA0, curA1);
            *reinterpret_cast<float2*>(&qB[s & 1][to0]) = make_float2(curB0, curB1);
        };
        // single-chain forward step (tail of the longer chain)
        auto fstep1 = [&](int s, int r, const float* fp, float (*q)[Tt],
                          float* e0, float* e1, int& eSum, float& c0out, float& c1out) {
            const float e0v = e0[r], e1v = e1[r];
            float2 fa = *reinterpret_cast<const float2*>(fp + (s + PD) * Tt + to0);
            e0[r] = __expf(fa.x); e1[r] = __expf(fa.y);
            __syncwarp();
            const ulonglong2* p = reinterpret_cast<const ulonglong2*>(q[(s - 1) & 1]);
            ulonglong2 v = p[0];
            float q0, td;
            unpack2(v.x, q0, td);
            u64 x0 = fma2(v.x, E2a[0], 0ull), x1 = fma2(v.y, E2a[1], 0ull);
            u64 y0 = fma2(v.x, E2b[0], 0ull), y1 = fma2(v.y, E2b[1], 0ull);
            #pragma unroll
            for (int j = 1; j < 16; ++j) {
                v = p[j];
                x0 = fma2(v.x, E2a[2 * j],     x0);
                x1 = fma2(v.y, E2a[2 * j + 1], x1);
                y0 = fma2(v.x, E2b[2 * j],     y0);
                y1 = fma2(v.y, E2b[2 * j + 1], y1);
            }
            const unsigned eb = __float_as_uint(q0) >> 23;
            eSum += (int)eb - 127;
            const float sc = __uint_as_float((254u - eb) << 23);
            float lo, hi;
            unpack2(add2(x0, x1), lo, hi); c0out = (lo + hi) * (e0v * sc);
            unpack2(add2(y0, y1), lo, hi); c1out = (lo + hi) * (e1v * sc);
            *reinterpret_cast<float2*>(&q[s & 1][to0]) = make_float2(c0out, c1out);
        };

        const int nmin = (hA < hB) ? hA : hB;
        int s = 1;
        for (; s + (PD - 1) <= nmin; ) {
            #pragma unroll
            for (int r = 0; r < PD; ++r) { fstep2(s, r); ++s; }
        }
        for (; s <= nmin; ++s) fstep2(s, (s - 1) & (PD - 1));
        for (int sa = s; sa <= hA; ++sa)
            fstep1(sa, (sa - 1) & (PD - 1), fAp, qA, eA0, eA1, eSumA, curA0, curA1);
        for (int sb = s; sb <= hB; ++sb)
            fstep1(sb, (sb - 1) & (PD - 1), fBp, qB, eB0, eB1, eSumB, curB0, curB1);

        // ---- publish P_h for both batches ----
        g_meet[bA][0][to0] = curA0;  g_meet[bA][0][to0 + 1] = curA1;
        g_meet[bB][0][to0] = curB0;  g_meet[bB][0][to0 + 1] = curB1;
        if (lane == 0) {
            g_meet[bA][0][64] = (float)eSumA; g_meet[bA][0][65] = cA0; g_meet[bA][0][66] = goldA;
            g_meet[bB][0][64] = (float)eSumB; g_meet[bB][0][65] = cB0; g_meet[bB][0][66] = goldB;
        }
    } else {
        // ---- backward co-vector halves of batches bA, bB ----
        // u_{L-1}[to] = exp(trans[to][STOP]) = hi half of E2x[31] (expE rows in regs)
        {
            float lo, u0, u1;
            unpack2(E2a[31], lo, u0);
            unpack2(E2b[31], lo, u1);
            curA0 = u0; curA1 = u1;
            curB0 = u0; curB1 = u1;
            float2 fa = *reinterpret_cast<const float2*>(fAp + (size_t)(LA - 1) * Tt + to0);
            *reinterpret_cast<float2*>(&qA[0][to0]) =
                make_float2(u0 * __expf(fa.x), u1 * __expf(fa.y));
            float2 fbv = *reinterpret_cast<const float2*>(fBp + (size_t)(LB - 1) * Tt + to0);
            *reinterpret_cast<float2*>(&qB[0][to0]) =
                make_float2(u0 * __expf(fbv.x), u1 * __expf(fbv.y));
        }
        const int nA = LA - 1 - hA;   // steps for chain A (>=127)
        const int nB = LB - 1 - hB;

        float eA0[PD], eA1[PD], eB0[PD], eB1[PD];
        #pragma unroll
        for (int r = 0; r < PD; ++r) {
            float2 fa = *reinterpret_cast<const float2*>(fAp + (size_t)(LA - 2 - r) * Tt + to0);
            eA0[r] = __expf(fa.x); eA1[r] = __expf(fa.y);
            float2 fbv = *reinterpret_cast<const float2*>(fBp + (size_t)(LB - 2 - r) * Tt + to0);
            eB0[r] = __expf(fbv.x); eB1[r] = __expf(fbv.y);
        }

        auto bstep2 = [&](int j, int r) {
            const float ea0 = eA0[r], ea1 = eA1[r], eb0 = eB0[r], eb1 = eB1[r];
            // prefetch rows (>= h-1-PD >= 0: safe)
            float2 fa = *reinterpret_cast<const float2*>(fAp + (size_t)(LA - 2 - j - PD) * Tt + to0);
            eA0[r] = __expf(fa.x); eA1[r] = __expf(fa.y);
            float2 fbv = *reinterpret_cast<const float2*>(fBp + (size_t)(LB - 2 - j - PD) * Tt + to0);
            eB0[r] = __expf(fbv.x); eB1[r] = __expf(fbv.y);

            __syncwarp();
            const ulonglong2* pA = reinterpret_cast<const ulonglong2*>(qA[j & 1]);
            const ulonglong2* pB = reinterpret_cast<const ulonglong2*>(qB[j & 1]);

            ulonglong2 vA = pA[0], vB = pB[0];
            float wa0, wb0, td;
            unpack2(vA.x, wa0, td);
            unpack2(vB.x, wb0, td);

            u64 xA0 = fma2(vA.x, E2a[0], 0ull), xA1 = fma2(vA.y, E2a[1], 0ull);
            u64 yA0 = fma2(vA.x, E2b[0], 0ull), yA1 = fma2(vA.y, E2b[1], 0ull);
            u64 xB0 = fma2(vB.x, E2a[0], 0ull), xB1 = fma2(vB.y, E2a[1], 0ull);
            u64 yB0 = fma2(vB.x, E2b[0], 0ull), yB1 = fma2(vB.y, E2b[1], 0ull);
            #pragma unroll
            for (int jj = 1; jj < 16; ++jj) {
                vA = pA[jj]; vB = pB[jj];
                xA0 = fma2(vA.x, E2a[2 * jj],     xA0);
                xB0 = fma2(vB.x, E2a[2 * jj],     xB0);
                xA1 = fma2(vA.y, E2a[2 * jj + 1], xA1);
                xB1 = fma2(vB.y, E2a[2 * jj + 1], xB1);
                yA0 = fma2(vA.x, E2b[2 * jj],     yA0);
                yB0 = fma2(vB.x, E2b[2 * jj],     yB0);
                yA1 = fma2(vA.y, E2b[2 * jj + 1], yA1);
                yB1 = fma2(vB.y, E2b[2 * jj + 1], yB1);
            }
            const unsigned ebA = __float_as_uint(wa0) >> 23;
            eSumA += (int)ebA - 127;
            const float scA = __uint_as_float((254u - ebA) << 23);
            const unsigned ebB = __float_as_uint(wb0) >> 23;
            eSumB += (int)ebB - 127;
            const float scB = __uint_as_float((254u - ebB) << 23);

            float lo, hi;
            unpack2(add2(xA0, xA1), lo, hi); curA0 = (lo + hi) * scA;
            unpack2(add2(yA0, yA1), lo, hi); curA1 = (lo + hi) * scA;
            unpack2(add2(xB0, xB1), lo, hi); curB0 = (lo + hi) * scB;
            unpack2(add2(yB0, yB1), lo, hi); curB1 = (lo + hi) * scB;
            *reinterpret_cast<float2*>(&qA[(j + 1) & 1][to0]) =
                make_float2(curA0 * ea0, curA1 * ea1);
            *reinterpret_cast<float2*>(&qB[(j + 1) & 1][to0]) =
                make_float2(curB0 * eb0, curB1 * eb1);
        };
        auto bstep1 = [&](int j, int r, const float* fp, float (*q)[Tt], int Lx,
                          float* e0, float* e1, int& eSum, float& c0out, float& c1out) {
            const float e0v = e0[r], e1v = e1[r];
            float2 fa = *reinterpret_cast<const float2*>(fp + (size_t)(Lx - 2 - j - PD) * Tt + to0);
            e0[r] = __expf(fa.x); e1[r] = __expf(fa.y);
            __syncwarp();
            const ulonglong2* p = reinterpret_cast<const ulonglong2*>(q[j & 1]);
            ulonglong2 v = p[0];
            float w0, td;
            unpack2(v.x, w0, td);
            u64 x0 = fma2(v.x, E2a[0], 0ull), x1 = fma2(v.y, E2a[1], 0ull);
            u64 y0 = fma2(v.x, E2b[0], 0ull), y1 = fma2(v.y, E2b[1], 0ull);
            #pragma unroll
            for (int jj = 1; jj < 16; ++jj) {
                v = p[jj];
                x0 = fma2(v.x, E2a[2 * jj],     x0);
                x1 = fma2(v.y, E2a[2 * jj + 1], x1);
                y0 = fma2(v.x, E2b[2 * jj],     y0);
                y1 = fma2(v.y, E2b[2 * jj + 1], y1);
            }
            const unsigned eb = __float_as_uint(w0) >> 23;
            eSum += (int)eb - 127;
            const float sc = __uint_as_float((254u - eb) << 23);
            float lo, hi;
            unpack2(add2(x0, x1), lo, hi); c0out = (lo + hi) * sc;
            unpack2(add2(y0, y1), lo, hi); c1out = (lo + hi) * sc;
            *reinterpret_cast<float2*>(&q[(j + 1) & 1][to0]) =
                make_float2(c0out * e0v, c1out * e1v);
        };

        const int nmin = (nA < nB) ? nA : nB;
        int j = 0;
        for (; j + PD <= nmin; ) {
            #pragma unroll
            for (int r = 0; r < PD; ++r) { bstep2(j, r); ++j; }
        }
        for (; j < nmin; ++j) bstep2(j, j & (PD - 1));
        for (int ja = j; ja < nA; ++ja)
            bstep1(ja, ja & (PD - 1), fAp, qA, LA, eA0, eA1, eSumA, curA0, curA1);
        for (int jb = j; jb < nB; ++jb)
            bstep1(jb, jb & (PD - 1), fBp, qB, LB, eB0, eB1, eSumB, curB0, curB1);

        // ---- publish u_h for both batches ----
        g_meet[bA][1][to0] = curA0;  g_meet[bA][1][to0 + 1] = curA1;
        g_meet[bB][1][to0] = curB0;  g_meet[bB][1][to0 + 1] = curB1;
        if (lane == 0) {
            g_meet[bA][1][64] = (float)eSumA;
            g_meet[bB][1][64] = (float)eSumB;
        }
    }

    // ---- rendezvous per batch: second arriver combines ----
    __threadfence();
    unsigned oA = 0, oB = 0;
    if (lane == 0) {
        oA = atomicAdd(&g_pair[bA], 1u);
        oB = atomicAdd(&g_pair[bB], 1u);
    }
    oA = __shfl_sync(0xffffffffu, oA, 0);
    oB = __shfl_sync(0xffffffffu, oB, 0);

    auto combine = [&](int b) -> unsigned {
        __threadfence();
        const float p0 = ldcg(&g_meet[b][0][to0]);
        const float p1 = ldcg(&g_meet[b][0][to0 + 1]);
        const float u0 = ldcg(&g_meet[b][1][to0]);
        const float u1 = ldcg(&g_meet[b][1][to0 + 1]);
        const float dot = warp_sum(p0 * u0 + p1 * u1);
        unsigned c = 0;
        if (lane == 0) {
            const float eF = ldcg(&g_meet[b][0][64]);
            const float c0 = ldcg(&g_meet[b][0][65]);
            const float gv = ldcg(&g_meet[b][0][66]);
            const float eB = ldcg(&g_meet[b][1][64]);
            g_partial[b] = c0 + (eF + eB) * LN2 + __logf(dot) - gv;
            g_pair[b] = 0;                      // reset for graph replay
            __threadfence();
            c = atomicAdd(&g_count, 1u);
        }
        return __shfl_sync(0xffffffffu, c, 0);
    };

    unsigned c1 = 0xfffffffeu, c2 = 0xfffffffeu;
    if (oA == 1u) c1 = combine(bA);
    if (oB == 1u) c2 = combine(bB);

    // ---- last combiner: deterministic fixed-order reduction over batches ----
    if (c1 == (unsigned)(Bb - 1) || c2 == (unsigned)(Bb - 1)) {
        __threadfence();
        float sum = 0.f;
        #pragma unroll
        for (int k = 0; k < Bb / 32; ++k)
            sum += ldcg(&g_partial[lane + k * 32]);
        sum = warp_sum(sum);
        if (lane == 0) {
            out[0] = sum;
            g_count = 0;                        // reset for graph replay
        }
    }
}

extern "C" void kernel_launch(void* const* d_in, const int* in_sizes, int n_in,
                              void* d_out, int out_size)
{
    (void)in_sizes; (void)n_in; (void)out_size;
    const float*         feats = (const float*)d_in[0];
    const unsigned char* mask  = (const unsigned char*)d_in[1];
    const int*           tags  = (const int*)d_in[2];
    const float*         trans = (const float*)d_in[3];

    prep_kernel<<<4, 1024>>>(trans);
    crf_kernel<<<Bb, 32>>>(feats, mask, tags, trans, (float*)d_out);
}

// round 12
// speedup vs baseline: 1.0429x; 1.0429x over previous
#include <cuda_runtime.h>

// CRF NLL: 3-segment split per sequence using rank-1 interior products.
// Per-step operator D_s E^T is strongly positive (Birkhoff contraction
// <=0.38/step), so the interior segment product M2 (>=85 steps) is
// numerically rank-1: M2 ~= (M2 e)(M2^T e)^T / (e^T M2 e)  (error ~1e-35).
// Z = Estop^T M3 M2 M1 P0 = (t^T u)(v^T P)/(e^T u) with
//   role0: P = M(1,a) P0        (fwd scan, E^T)
//   role1: u = M(a+1,b) e       (fwd scan from ones, E^T)
//   role2: v = M(a+1,b)^T e     (bwd scan from ones, E)
//   role3: t = M(b+1,L-1)^T Es  (bwd scan from Estop, E)
// 2048 single-warp blocks (R10's proven barrier-free body, exact
// power-of-2 rescaling). Depth 256 -> ~171, chains 1024 -> 2048.

constexpr int Bb = 512;
constexpr int Ss = 512;
constexpr int Tt = 64;
constexpr int START = Tt - 2;
constexpr int STOP  = Tt - 1;
constexpr int PD    = 4;
constexpr float LN2 = 0.69314718055994531f;

__device__ __align__(16) float g_expE [Tt * Tt];   // exp(trans) [from][to]
__device__ __align__(16) float g_expET[Tt * Tt];   // transpose  [to][from]
__device__ float g_meet[Bb][4][68];  // vec[64], [64]=eSum, role0: [65]=c0,[66]=gold
__device__ float g_partial[Bb];
__device__ unsigned g_pair[Bb];      // zero-initialized
__device__ unsigned g_count = 0;

typedef unsigned long long u64;

static __device__ __forceinline__ u64 fma2(u64 a, u64 b, u64 c) {
    u64 d;
    asm("fma.rn.f32x2 %0, %1, %2, %3;" : "=l"(d) : "l"(a), "l"(b), "l"(c));
    return d;
}
static __device__ __forceinline__ u64 add2(u64 a, u64 b) {
    u64 d;
    asm("add.rn.f32x2 %0, %1, %2;" : "=l"(d) : "l"(a), "l"(b));
    return d;
}
static __device__ __forceinline__ u64 pack2(float lo, float hi) {
    u64 d;
    asm("mov.b64 %0, {%1, %2};" : "=l"(d) : "f"(lo), "f"(hi));
    return d;
}
static __device__ __forceinline__ void unpack2(u64 v, float& lo, float& hi) {
    asm("mov.b64 {%0, %1}, %2;" : "=f"(lo), "=f"(hi) : "l"(v));
}
static __device__ __forceinline__ float ldcg(const float* p) {
    float v;
    asm volatile("ld.global.cg.f32 %0, [%1];" : "=f"(v) : "l"(p));
    return v;
}
static __device__ __forceinline__ float warp_sum(float v) {
    #pragma unroll
    for (int off = 16; off > 0; off >>= 1)
        v += __shfl_xor_sync(0xffffffffu, v, off);
    return v;
}
static __device__ __forceinline__ int warp_sum_i(int v) {
    #pragma unroll
    for (int off = 16; off > 0; off >>= 1)
        v += __shfl_xor_sync(0xffffffffu, v, off);
    return v;
}

__global__ void prep_kernel(const float* __restrict__ trans) {
    int i = blockIdx.x * blockDim.x + threadIdx.x;   // 0..4095
    float e = __expf(trans[i]);
    g_expE[i] = e;
    g_expET[(i & (Tt - 1)) * Tt + (i >> 6)] = e;
}

__global__ __launch_bounds__(32) void crf_kernel(
    const float* __restrict__ feats,
    const unsigned char* __restrict__ mask8,
    const int* __restrict__ tags,
    const float* __restrict__ trans,
    float* __restrict__ out)
{
    const int role = blockIdx.x >> 9;          // 0..3
    const int b    = blockIdx.x & (Bb - 1);
    const int lane = threadIdx.x;              // 0..31
    const int to0  = 2 * lane;

    __shared__ __align__(16) float qbuf[2][Tt];

    // ---- mask layout probe (uint8 vs int32) + sequence length ----
    const int* mask32 = reinterpret_cast<const int*>(mask8);
    const bool is32 = (mask8[0] == 1 && mask8[1] == 0 && mask8[2] == 0 && mask8[3] == 0);

    int cnt = 0;
    #pragma unroll
    for (int k = 0; k < Ss / 32; ++k) {
        int s  = lane + k * 32;
        int mv = is32 ? mask32[b * Ss + s] : (int)mask8[b * Ss + s];
        cnt += (mv != 0);
    }
    const int L  = warp_sum_i(cnt);            // >= 256
    const int aB = L / 3;                      // >= 85
    const int bB = (2 * L) / 3;

    const float* fb = feats + (size_t)b * Ss * Tt;

    // ---- E registers (row 'to0'/'to0+1' of chosen orientation) ----
    const float* Es = (role < 2) ? g_expET : g_expE;
    u64 E2a[Tt / 2], E2b[Tt / 2];
    {
        const float4* ra = reinterpret_cast<const float4*>(Es + to0 * Tt);
        const float4* rb = reinterpret_cast<const float4*>(Es + (to0 + 1) * Tt);
        #pragma unroll
        for (int k = 0; k < 16; ++k) {
            float4 v = ra[k];
            E2a[2 * k]     = pack2(v.x, v.y);
            E2a[2 * k + 1] = pack2(v.z, v.w);
            float4 u = rb[k];
            E2b[2 * k]     = pack2(u.x, u.y);
            E2b[2 * k + 1] = pack2(u.z, u.w);
        }
    }

    int   eSum = 0;
    int   pb   = 0;
    float cur0 = 0.f, cur1 = 0.f;
    float c0v  = 0.f, goldv = 0.f;

    // ---- fused matvec + rescale + store (fwd: *ef after; bwd: *ef into store) ----
    auto fstep = [&](float ea, float eb2) {
        __syncwarp();
        const ulonglong2* qp = reinterpret_cast<const ulonglong2*>(qbuf[pb]);
        ulonglong2 v = qp[0];
        float q0, td;
        unpack2(v.x, q0, td);
        u64 x0 = fma2(v.x, E2a[0], 0ull), x1 = fma2(v.y, E2a[1], 0ull);
        u64 y0 = fma2(v.x, E2b[0], 0ull), y1 = fma2(v.y, E2b[1], 0ull);
        #pragma unroll
        for (int j = 1; j < 16; ++j) {
            v = qp[j];
            x0 = fma2(v.x, E2a[2 * j],     x0);
            x1 = fma2(v.y, E2a[2 * j + 1], x1);
            y0 = fma2(v.x, E2b[2 * j],     y0);
            y1 = fma2(v.y, E2b[2 * j + 1], y1);
        }
        const unsigned ebits = __float_as_uint(q0) >> 23;
        eSum += (int)ebits - 127;
        const float sc = __uint_as_float((254u - ebits) << 23);
        float lo, hi;
        unpack2(add2(x0, x1), lo, hi); cur0 = (lo + hi) * (ea * sc);
        unpack2(add2(y0, y1), lo, hi); cur1 = (lo + hi) * (eb2 * sc);
        pb ^= 1;
        *reinterpret_cast<float2*>(&qbuf[pb][to0]) = make_float2(cur0, cur1);
    };
    auto bstep = [&](float ea, float eb2) {
        __syncwarp();
        const ulonglong2* qp = reinterpret_cast<const ulonglong2*>(qbuf[pb]);
        ulonglong2 v = qp[0];
        float w0, td;
        unpack2(v.x, w0, td);
        u64 x0 = fma2(v.x, E2a[0], 0ull), x1 = fma2(v.y, E2a[1], 0ull);
        u64 y0 = fma2(v.x, E2b[0], 0ull), y1 = fma2(v.y, E2b[1], 0ull);
        #pragma unroll
        for (int j = 1; j < 16; ++j) {
            v = qp[j];
            x0 = fma2(v.x, E2a[2 * j],     x0);
            x1 = fma2(v.y, E2a[2 * j + 1], x1);
            y0 = fma2(v.x, E2b[2 * j],     y0);
            y1 = fma2(v.y, E2b[2 * j + 1], y1);
        }
        const unsigned ebits = __float_as_uint(w0) >> 23;
        eSum += (int)ebits - 127;
        const float sc = __uint_as_float((254u - ebits) << 23);
        float lo, hi;
        unpack2(add2(x0, x1), lo, hi); cur0 = (lo + hi) * sc;
        unpack2(add2(y0, y1), lo, hi); cur1 = (lo + hi) * sc;
        pb ^= 1;
        *reinterpret_cast<float2*>(&qbuf[pb][to0]) = make_float2(cur0 * ea, cur1 * eb2);
    };

    // ---- scan drivers (ef exp'd at prefetch time; rows stay in [0,Ss)) ----
    auto fwd_scan = [&](int first, int last) {
        float e0[PD], e1[PD];
        #pragma unroll
        for (int r = 0; r < PD; ++r) {
            float2 f = *reinterpret_cast<const float2*>(fb + (size_t)(first + r) * Tt + to0);
            e0[r] = __expf(f.x); e1[r] = __expf(f.y);
        }
        int s = first;
        for (; s + (PD - 1) <= last; ) {
            #pragma unroll
            for (int r = 0; r < PD; ++r) {
                const float ea = e0[r], eb2 = e1[r];
                float2 f = *reinterpret_cast<const float2*>(fb + (size_t)(s + PD) * Tt + to0);
                e0[r] = __expf(f.x); e1[r] = __expf(f.y);
                fstep(ea, eb2);
                ++s;
            }
        }
        for (; s <= last; ++s) {
            int r = (s - first) & (PD - 1);
            fstep(e0[r], e1[r]);
        }
    };
    auto bwd_scan = [&](int top, int n) {
        float e0[PD], e1[PD];
        #pragma unroll
        for (int r = 0; r < PD; ++r) {
            float2 f = *reinterpret_cast<const float2*>(fb + (size_t)(top - 1 - r) * Tt + to0);
            e0[r] = __expf(f.x); e1[r] = __expf(f.y);
        }
        int j = 0;
        for (; j + PD <= n; ) {
            #pragma unroll
            for (int r = 0; r < PD; ++r) {
                const float ea = e0[r], eb2 = e1[r];
                float2 f = *reinterpret_cast<const float2*>(
                    fb + (size_t)(top - 1 - j - PD) * Tt + to0);
                e0[r] = __expf(f.x); e1[r] = __expf(f.y);
                bstep(ea, eb2);
                ++j;
            }
        }
        for (; j < n; ++j) {
            int r = j & (PD - 1);
            bstep(e0[r], e1[r]);
        }
    };

    if (role == 0) {
        // gold path score (full sequence)
        const int* tg = tags + b * Ss;
        float gsum = 0.f;
        for (int s = lane; s < L; s += 32) {
            int t1 = tg[s];
            int t0 = (s == 0) ? START : tg[s - 1];
            gsum += fb[s * Tt + t1] + trans[t0 * Tt + t1];
        }
        goldv = warp_sum(gsum) + trans[tg[L - 1] * Tt + STOP];

        // P_0 = exp(f_0 + T[START,:]) / exp(c0)
        c0v = fb[0] + trans[START * Tt];
        float2 f0 = *reinterpret_cast<const float2*>(fb + to0);
        qbuf[0][to0]     = __expf(f0.x + trans[START * Tt + to0]     - c0v);
        qbuf[0][to0 + 1] = __expf(f0.y + trans[START * Tt + to0 + 1] - c0v);
        fwd_scan(1, aB);
    } else if (role == 1) {
        qbuf[0][to0] = 1.f;  qbuf[0][to0 + 1] = 1.f;
        fwd_scan(aB + 1, bB);
    } else if (role == 2) {
        float2 f0 = *reinterpret_cast<const float2*>(fb + (size_t)bB * Tt + to0);
        qbuf[0][to0]     = __expf(f0.x);
        qbuf[0][to0 + 1] = __expf(f0.y);
        bwd_scan(bB, bB - aB);
    } else {
        float lo, u0, u1;
        unpack2(E2a[31], lo, u0);   // E[to0][STOP]
        unpack2(E2b[31], lo, u1);   // E[to0+1][STOP]
        cur0 = u0;  cur1 = u1;
        float2 f0 = *reinterpret_cast<const float2*>(fb + (size_t)(L - 1) * Tt + to0);
        qbuf[0][to0]     = u0 * __expf(f0.x);
        qbuf[0][to0 + 1] = u1 * __expf(f0.y);
        bwd_scan(L - 1, L - 1 - bB);
    }

    // ---- publish ----
    {
        float* m = g_meet[b][role];
        m[to0]     = cur0;
        m[to0 + 1] = cur1;
        if (lane == 0) {
            m[64] = (float)eSum;
            if (role == 0) { m[65] = c0v; m[66] = goldv; }
        }
    }

    // ---- rendezvous: 4th arriver combines ----
    __threadfence();
    unsigned old = 0;
    if (lane == 0) old = atomicAdd(&g_pair[b], 1u);
    old = __shfl_sync(0xffffffffu, old, 0);
    if (old != 3u) return;

    __threadfence();
    const float p0  = ldcg(&g_meet[b][0][to0]);
    const float p1  = ldcg(&g_meet[b][0][to0 + 1]);
    const float uu0 = ldcg(&g_meet[b][1][to0]);
    const float uu1 = ldcg(&g_meet[b][1][to0 + 1]);
    const float v0  = ldcg(&g_meet[b][2][to0]);
    const float v1  = ldcg(&g_meet[b][2][to0 + 1]);
    const float t0  = ldcg(&g_meet[b][3][to0]);
    const float t1  = ldcg(&g_meet[b][3][to0 + 1]);
    const float dot1 = warp_sum(v0 * p0 + v1 * p1);     // v^T P
    const float dot2 = warp_sum(t0 * uu0 + t1 * uu1);   // t^T u
    const float den  = warp_sum(uu0 + uu1);             // e^T u

    unsigned c = 0;
    if (lane == 0) {
        const float S0 = ldcg(&g_meet[b][0][64]);
        const float S2 = ldcg(&g_meet[b][2][64]);
        const float S3 = ldcg(&g_meet[b][3][64]);
        const float c0 = ldcg(&g_meet[b][0][65]);
        const float gv = ldcg(&g_meet[b][0][66]);
        const float logZ = c0 + (S0 + S2 + S3) * LN2
                         + __logf(dot1) + __logf(dot2) - __logf(den);
        g_partial[b] = logZ - gv;
        g_pair[b] = 0;                       // reset for graph replay
        __threadfence();
        c = atomicAdd(&g_count, 1u);
    }
    c = __shfl_sync(0xffffffffu, c, 0);

    // ---- last combiner: deterministic fixed-order reduction over batches ----
    if (c == (unsigned)(Bb - 1)) {
        __threadfence();
        float sum = 0.f;
        #pragma unroll
        for (int k = 0; k < Bb / 32; ++k)
            sum += ldcg(&g_partial[lane + k * 32]);
        sum = warp_sum(sum);
        if (lane == 0) {
            out[0] = sum;
            g_count = 0;                     // reset for graph replay
        }
    }
}

extern "C" void kernel_launch(void* const* d_in, const int* in_sizes, int n_in,
                              void* d_out, int out_size)
{
    (void)in_sizes; (void)n_in; (void)out_size;
    const float*         feats = (const float*)d_in[0];
    const unsigned char* mask  = (const unsigned char*)d_in[1];
    const int*           tags  = (const int*)d_in[2];
    const float*         trans = (const float*)d_in[3];

    prep_kernel<<<4, 1024>>>(trans);
    crf_kernel<<<4 * Bb, 32>>>(feats, mask, tags, trans, (float*)d_out);
}

// round 13
// speedup vs baseline: 1.2949x; 1.2416x over previous
#include <cuda_runtime.h>

// CRF NLL, bidirectional exp-domain scan, single-warp chains (R10 topology)
// with the prefetch fixed: the feats ring holds RAW float2 and __expf is
// applied at CONSUME time, so the LDG -> use distance is PD full steps and
// the DRAM latency is actually hidden (previous rounds exp'd right after
// the load, stalling every step on the long scoreboard).
// 1024 blocks x 32 threads: block b (<512) = forward half of batch b (P_h);
// block b+512 = backward co-vector half (u_h). answer = log(dot(P_h,u_h)).
// Exact power-of-2 rescaling; no CTA barriers.

constexpr int Bb = 512;
constexpr int Ss = 512;
constexpr int Tt = 64;
constexpr int START = Tt - 2;
constexpr int STOP  = Tt - 1;
constexpr int PD    = 4;     // feats prefetch depth (steps)
constexpr float LN2 = 0.69314718055994531f;

__device__ float g_meet[Bb][2][68];  // [.][0]: P_h,64=eF,65=c0,66=gold ; [.][1]: u_h,64=eB
__device__ float g_partial[Bb];
__device__ unsigned g_pair[Bb];      // zero-initialized
__device__ unsigned g_count = 0;

typedef unsigned long long u64;

static __device__ __forceinline__ u64 fma2(u64 a, u64 b, u64 c) {
    u64 d;
    asm("fma.rn.f32x2 %0, %1, %2, %3;" : "=l"(d) : "l"(a), "l"(b), "l"(c));
    return d;
}
static __device__ __forceinline__ u64 add2(u64 a, u64 b) {
    u64 d;
    asm("add.rn.f32x2 %0, %1, %2;" : "=l"(d) : "l"(a), "l"(b));
    return d;
}
static __device__ __forceinline__ u64 pack2(float lo, float hi) {
    u64 d;
    asm("mov.b64 %0, {%1, %2};" : "=l"(d) : "f"(lo), "f"(hi));
    return d;
}
static __device__ __forceinline__ void unpack2(u64 v, float& lo, float& hi) {
    asm("mov.b64 {%0, %1}, %2;" : "=f"(lo), "=f"(hi) : "l"(v));
}
static __device__ __forceinline__ float ldcg(const float* p) {
    float v;
    asm volatile("ld.global.cg.f32 %0, [%1];" : "=f"(v) : "l"(p));
    return v;
}
static __device__ __forceinline__ float warp_sum(float v) {
    #pragma unroll
    for (int off = 16; off > 0; off >>= 1)
        v += __shfl_xor_sync(0xffffffffu, v, off);
    return v;
}
static __device__ __forceinline__ int warp_sum_i(int v) {
    #pragma unroll
    for (int off = 16; off > 0; off >>= 1)
        v += __shfl_xor_sync(0xffffffffu, v, off);
    return v;
}

__global__ __launch_bounds__(32) void crf_kernel(
    const float* __restrict__ feats,
    const unsigned char* __restrict__ mask8,
    const int* __restrict__ tags,
    const float* __restrict__ trans,
    float* __restrict__ out)
{
    const bool isF = (blockIdx.x < Bb);
    const int  b   = isF ? blockIdx.x : blockIdx.x - Bb;
    const int  lane = threadIdx.x;      // 0..31
    const int  to0  = 2 * lane;         // owned tags

    __shared__ __align__(16) float qbuf[2][Tt];   // q / w vector, double-buffered

    // ---- mask layout probe (uint8 vs int32) + sequence length ----
    const int* mask32 = reinterpret_cast<const int*>(mask8);
    const bool is32 = (mask8[0] == 1 && mask8[1] == 0 && mask8[2] == 0 && mask8[3] == 0);

    int cnt = 0;
    #pragma unroll
    for (int k = 0; k < Ss / 32; ++k) {
        int s  = lane + k * 32;
        int mv = is32 ? mask32[b * Ss + s] : (int)mask8[b * Ss + s];
        cnt += (mv != 0);
    }
    const int L = warp_sum_i(cnt);   // >= 256
    const int h = L / 2;             // forward: steps 1..h ; backward: L-1..h+1

    const float* fb = feats + (size_t)b * Ss * Tt;
    const int*   tg = tags + b * Ss;

    float gold = 0.f, c0f = 0.f;
    int   eSum = 0;
    float cur0 = 0.f, cur1 = 0.f;

    // ---- E pairs: forward needs columns {to0,to0+1}; backward needs rows ----
    u64 E2a[Tt / 2], E2b[Tt / 2];
    if (isF) {
        #pragma unroll
        for (int k = 0; k < Tt / 2; ++k) {
            E2a[k] = pack2(__expf(trans[(2 * k) * Tt + to0]),
                           __expf(trans[(2 * k + 1) * Tt + to0]));
            E2b[k] = pack2(__expf(trans[(2 * k) * Tt + to0 + 1]),
                           __expf(trans[(2 * k + 1) * Tt + to0 + 1]));
        }
    } else {
        #pragma unroll
        for (int k = 0; k < Tt / 2; ++k) {
            E2a[k] = pack2(__expf(trans[to0 * Tt + 2 * k]),
                           __expf(trans[to0 * Tt + 2 * k + 1]));
            E2b[k] = pack2(__expf(trans[(to0 + 1) * Tt + 2 * k]),
                           __expf(trans[(to0 + 1) * Tt + 2 * k + 1]));
        }
    }

    // shared FMA core
    auto matvec = [&](const ulonglong2* qp, float& o0, float& o1, float& w0out) {
        ulonglong2 v = qp[0];
        float w0, wd;
        unpack2(v.x, w0, wd);
        w0out = w0;
        u64 a0 = fma2(v.x, E2a[0], 0ull);
        u64 a1 = fma2(v.y, E2a[1], 0ull);
        u64 b0 = fma2(v.x, E2b[0], 0ull);
        u64 b1 = fma2(v.y, E2b[1], 0ull);
        #pragma unroll
        for (int j = 1; j < 16; ++j) {
            v = qp[j];
            a0 = fma2(v.x, E2a[2 * j],     a0);
            a1 = fma2(v.y, E2a[2 * j + 1], a1);
            b0 = fma2(v.x, E2b[2 * j],     b0);
            b1 = fma2(v.y, E2b[2 * j + 1], b1);
        }
        float alo, ahi, blo, bhi;
        unpack2(add2(a0, a1), alo, ahi);
        unpack2(add2(b0, b1), blo, bhi);
        o0 = alo + ahi;
        o1 = blo + bhi;
    };

    if (isF) {
        // ---- gold path score (full sequence) ----
        float gsum = 0.f;
        for (int s = lane; s < L; s += 32) {
            int t1 = tg[s];
            int t0 = (s == 0) ? START : tg[s - 1];
            gsum += fb[s * Tt + t1] + trans[t0 * Tt + t1];
        }
        gold = warp_sum(gsum) + trans[tg[L - 1] * Tt + STOP];

        // ---- init: P_0 = exp(f_0 + T[START,:]), normalized by c0 ----
        const float c0 = fb[0] + trans[START * Tt];
        c0f = c0;
        {
            float2 f0 = *reinterpret_cast<const float2*>(fb + to0);
            float2 q0;
            q0.x = __expf(f0.x + trans[START * Tt + to0]     - c0);
            q0.y = __expf(f0.y + trans[START * Tt + to0 + 1] - c0);
            *reinterpret_cast<float2*>(&qbuf[0][to0]) = q0;
        }

        // RAW feats ring (exp applied at consume time)
        float2 fp[PD];
        #pragma unroll
        for (int r = 0; r < PD; ++r)
            fp[r] = *reinterpret_cast<const float2*>(fb + (1 + r) * Tt + to0);

        auto step = [&](int s, float2 f) {
            const float ea = __expf(f.x);   // MUFU issues early, result needed
            const float eb = __expf(f.y);   // only after the FMA block
            __syncwarp();
            const ulonglong2* qp = reinterpret_cast<const ulonglong2*>(qbuf[(s - 1) & 1]);
            float o0, o1, q0;
            matvec(qp, o0, o1, q0);
            const unsigned ebits = __float_as_uint(q0) >> 23;
            eSum += (int)ebits - 127;
            const float scale = __uint_as_float((254u - ebits) << 23);
            cur0 = o0 * (ea * scale);
            cur1 = o1 * (eb * scale);
            *reinterpret_cast<float2*>(&qbuf[s & 1][to0]) = make_float2(cur0, cur1);
        };

        const int end = h + 1;   // steps 1..h
        int s = 1;
        for (; s + (PD - 1) < end; ) {
            #pragma unroll
            for (int r = 0; r < PD; ++r) {
                const float2 f = fp[r];
                // prefetch raw (s+PD <= h+PD < Ss: safe)
                fp[r] = *reinterpret_cast<const float2*>(fb + (s + PD) * Tt + to0);
                step(s, f);
                ++s;
            }
        }
        for (; s < end; ++s) {
            step(s, fp[(s - 1) & (PD - 1)]);
        }

        // ---- publish P_h ----
        g_meet[b][0][to0]     = cur0;
        g_meet[b][0][to0 + 1] = cur1;
        if (lane == 0) {
            g_meet[b][0][64] = (float)eSum;
            g_meet[b][0][65] = c0f;
            g_meet[b][0][66] = gold;
        }
    } else {
        // ---- backward: u_{L-1} = Estop; w_t = u_t . ef_t; u_{t-1} = E w_t ----
        {
            float2 f0 = *reinterpret_cast<const float2*>(fb + (size_t)(L - 1) * Tt + to0);
            cur0 = __expf(trans[to0 * Tt + STOP]);
            cur1 = __expf(trans[(to0 + 1) * Tt + STOP]);
            *reinterpret_cast<float2*>(&qbuf[0][to0]) =
                make_float2(cur0 * __expf(f0.x), cur1 * __expf(f0.y));
        }

        const int nB = L - 1 - h;   // >= 127
        float2 fp[PD];
        #pragma unroll
        for (int r = 0; r < PD; ++r)
            fp[r] = *reinterpret_cast<const float2*>(fb + (size_t)(L - 2 - r) * Tt + to0);

        auto bstep = [&](int j, float2 f) {
            const float ea = __expf(f.x);
            const float eb = __expf(f.y);
            __syncwarp();
            const ulonglong2* qp = reinterpret_cast<const ulonglong2*>(qbuf[j & 1]);
            float o0, o1, w0;
            matvec(qp, o0, o1, w0);
            const unsigned ebits = __float_as_uint(w0) >> 23;
            eSum += (int)ebits - 127;
            const float scale = __uint_as_float((254u - ebits) << 23);
            cur0 = o0 * scale;          // u_{t-1}[to0]
            cur1 = o1 * scale;
            *reinterpret_cast<float2*>(&qbuf[(j + 1) & 1][to0]) =
                make_float2(cur0 * ea, cur1 * eb);
        };

        int j = 0;
        for (; j + (PD - 1) < nB; ) {
            #pragma unroll
            for (int r = 0; r < PD; ++r) {
                const float2 f = fp[r];
                // prefetch raw (L-2-j-PD >= h-3 >= 0: safe)
                fp[r] = *reinterpret_cast<const float2*>(
                    fb + (size_t)(L - 2 - j - PD) * Tt + to0);
                bstep(j, f);
                ++j;
            }
        }
        for (; j < nB; ++j) {
            bstep(j, fp[j & (PD - 1)]);
        }

        // ---- publish u_h ----
        g_meet[b][1][to0]     = cur0;
        g_meet[b][1][to0 + 1] = cur1;
        if (lane == 0) g_meet[b][1][64] = (float)eSum;
    }

    // ---- pair rendezvous: second arriver combines ----
    __threadfence();
    unsigned old = 0;
    if (lane == 0) old = atomicAdd(&g_pair[b], 1u);
    old = __shfl_sync(0xffffffffu, old, 0);
    if (old != 1u) return;   // first arriver exits

    __threadfence();
    const float* o = &g_meet[b][isF ? 1 : 0][0];
    float dot = warp_sum(cur0 * ldcg(o + to0) + cur1 * ldcg(o + to0 + 1));

    unsigned c = 0;
    if (lane == 0) {
        float eF, eB, c0v, gv;
        if (isF) {
            eF = (float)eSum; c0v = c0f; gv = gold;
            eB = ldcg(&g_meet[b][1][64]);
        } else {
            eB = (float)eSum;
            eF  = ldcg(&g_meet[b][0][64]);
            c0v = ldcg(&g_meet[b][0][65]);
            gv  = ldcg(&g_meet[b][0][66]);
        }
        g_partial[b] = c0v + (eF + eB) * LN2 + __logf(dot) - gv;
        g_pair[b] = 0;                       // reset for graph replay
        __threadfence();
        c = atomicAdd(&g_count, 1u);
    }
    c = __shfl_sync(0xffffffffu, c, 0);

    // ---- last combiner: deterministic fixed-order reduction over batches ----
    if (c == (unsigned)(Bb - 1)) {
        __threadfence();
        float sum = 0.f;
        #pragma unroll
        for (int k = 0; k < Bb / 32; ++k)
            sum += ldcg(&g_partial[lane + k * 32]);
        sum = warp_sum(sum);
        if (lane == 0) {
            out[0] = sum;
            g_count = 0;                     // reset for graph replay
        }
    }
}

extern "C" void kernel_launch(void* const* d_in, const int* in_sizes, int n_in,
                              void* d_out, int out_size)
{
    (void)in_sizes; (void)n_in; (void)out_size;
    const float*         feats = (const float*)d_in[0];
    const unsigned char* mask  = (const unsigned char*)d_in[1];
    const int*           tags  = (const int*)d_in[2];
    const float*         trans = (const float*)d_in[3];

    crf_kernel<<<2 * Bb, 32>>>(feats, mask, tags, trans, (float*)d_out);
}